// round 13
// baseline (speedup 1.0000x reference)
#include <cuda_runtime.h>
#include <cuda_fp16.h>

// DynamicRouting: B=128, IN=2048, OUT=32, POSE=4, 3 routing iterations.
// poses_out [B,32,4] followed by activations_out [B,32] in d_out.
//
// Pass 0 reads fp32 votes (DRAM, streaming, evict_first) and writes an fp16
// copy into a 64 MB __device__ scratch (evict_last -> L2-resident).
// Hot passes 1-2 stream the fp16 copy with a depth-1 software pipeline using
// two NAMED uint4 registers (no arrays / no pointer ping-pong: those demote
// to local memory and caused the R11/R12 spill catastrophe).
// Softmax over the 32 lanes: integer REDUX.SUM on 2^10 fixed-point exp.

#define NB 128
#define NI 2048
#define NO 32
#define NP 4
#define EPSF 1e-7f
#define NWARPS 32
#define NTHREADS (NWARPS * 32)
#define NQUAD 16
#define NSTEP 32            // 16-byte steps per thread per pass (2 votes each)

typedef unsigned long long u64;
typedef unsigned int u32;

// 64 MB fp16 vote cache, 32B-slot layout (quad q at ct + q*512 halves;
// step j at ct + (j>>1)*512 + (j&1)*8). Thread-private RAW.
__device__ __align__(32) __half vcache[(size_t)NB * NI * NO * NP];

__device__ __forceinline__ u32 h2_to_u32(__half2 h) {
    union { __half2 h; u32 u; } cvt; cvt.h = h; return cvt.u;
}
__device__ __forceinline__ __half2 u32_to_h2(u32 u) {
    union { u32 u; __half2 h; } cvt; cvt.u = u; return cvt.h;
}
__device__ __forceinline__ float ex2_fast(float x) {
    float r;
    asm("ex2.approx.ftz.f32 %0, %1;" : "=f"(r) : "f"(x));
    return r;
}

// fp32 vote load: read-only, streaming (evict_first).
__device__ __forceinline__ float4 ldg_stream(const float4* p, u64 pol) {
    float4 v;
    asm("ld.global.nc.L2::cache_hint.v4.f32 {%0,%1,%2,%3}, [%4], %5;"
        : "=f"(v.x), "=f"(v.y), "=f"(v.z), "=f"(v.w)
        : "l"(p), "l"(pol));
    return v;
}
// 16-byte scratch store with evict_last policy.
__device__ __forceinline__ void st_cache4(__half* p, u32 a, u32 b, u32 c, u32 d, u64 pol) {
    asm volatile("st.global.L2::cache_hint.v4.b32 [%0], {%1,%2,%3,%4}, %5;"
                 :: "l"(p), "r"(a), "r"(b), "r"(c), "r"(d), "l"(pol)
                 : "memory");
}
// 16-byte scratch load with evict_last policy, into a named uint4.
__device__ __forceinline__ uint4 ld_cache4(const __half* p, u64 pol) {
    uint4 r;
    asm("ld.global.nc.L2::cache_hint.v4.b32 {%0,%1,%2,%3}, [%4], %5;"
        : "=r"(r.x), "=r"(r.y), "=r"(r.z), "=r"(r.w)
        : "l"(p), "l"(pol));
    return r;
}

__global__ __launch_bounds__(NTHREADS, 1)
void routing_kernel(const float4* __restrict__ votes, float* __restrict__ out) {
    const int b    = blockIdx.x;
    const int tid  = threadIdx.x;
    const int w    = tid >> 5;
    const int lane = tid & 31;      // lane == output-capsule index o

    __shared__ float4 part4[NWARPS][NO];   // per-warp partial s: 16 KB
    __shared__ float4 vsh4[NO];            // squashed v of current iter
    __shared__ float  s_sh[NO * NP];       // reduced s

    u64 pol_first, pol_last;
    asm("createpolicy.fractional.L2::evict_first.b64 %0, 1.0;" : "=l"(pol_first));
    asm("createpolicy.fractional.L2::evict_last.b64 %0, 1.0;"  : "=l"(pol_last));

    const float4* vb = votes + (size_t)b * (NI * NO);
    // Thread's scratch: quad q at ct + q*512 halves; step j at
    // ct + (j>>1)*512 + (j&1)*8.
    __half* ct = vcache + (size_t)b * (NI * NO * NP)
                        + ((size_t)(w * NQUAD) * 32 + lane) * 16;

    // Accumulated logit vector, pre-scaled by log2(e):
    // after it0: wvs = v1*l2e; after it1: wvs = (v1+v2)*l2e.
    float4 wvs = make_float4(0.f, 0.f, 0.f, 0.f);
    const float l2e = 1.44269504f;

#pragma unroll
    for (int it = 0; it < 3; ++it) {
        float ax = 0.f, ay = 0.f, az = 0.f, aw = 0.f;

        // Two-vote compute step on a named uint4 (lambda keeps regs named).
        auto compute2 = [&](uint4 pk) {
#pragma unroll
            for (int h = 0; h < 2; ++h) {
                float2 f01 = __half22float2(u32_to_h2(h ? pk.z : pk.x));
                float2 f23 = __half22float2(u32_to_h2(h ? pk.w : pk.y));
                float t = 10.0f;                      // bias folded into dot
                t = fmaf(f01.x, wvs.x, t);
                t = fmaf(f01.y, wvs.y, t);
                t = fmaf(f23.x, wvs.z, t);
                t = fmaf(f23.y, wvs.w, t);
                float ef = ex2_fast(t);               // e^bij * 2^10
                u32   u  = __float2uint_rn(ef);
                u32   s  = __reduce_add_sync(0xffffffffu, u);
                float sf = fmaxf(__uint2float_rn(s), 1.0f);
                float c  = __fdividef(ef, sf);        // 2^10 cancels
                ax = fmaf(c, f01.x, ax);
                ay = fmaf(c, f01.y, ay);
                az = fmaf(c, f23.x, az);
                aw = fmaf(c, f23.y, aw);
            }
        };

        if (it == 0) {
            // fp32 streaming pass; uniform c = 1/32; write fp16 cache.
#pragma unroll 2
            for (int q = 0; q < NQUAD; ++q) {
                u32 pk[8];
#pragma unroll
                for (int h = 0; h < 4; ++h) {
                    const int i = w + 32 * (4 * q + h);
                    float4 vt = ldg_stream(&vb[i * NO + lane], pol_first);
                    pk[2 * h + 0] = h2_to_u32(__floats2half2_rn(vt.x, vt.y));
                    pk[2 * h + 1] = h2_to_u32(__floats2half2_rn(vt.z, vt.w));
                    ax += vt.x; ay += vt.y; az += vt.z; aw += vt.w;
                }
                __half* sp = ct + (size_t)q * 512;
                st_cache4(sp,     pk[0], pk[1], pk[2], pk[3], pol_last);
                st_cache4(sp + 8, pk[4], pk[5], pk[6], pk[7], pol_last);
            }
            ax *= (1.0f / 32.0f); ay *= (1.0f / 32.0f);
            az *= (1.0f / 32.0f); aw *= (1.0f / 32.0f);
        } else {
            // Depth-1 pipelined fp16 pass with NAMED ping-pong registers.
            uint4 rA = ld_cache4(ct, pol_last);          // step 0
            uint4 rB;
#pragma unroll
            for (int j = 0; j < NSTEP; j += 2) {
                // load odd step j+1 while computing even step j
                rB = ld_cache4(ct + ((j + 1) >> 1) * 512 + ((j + 1) & 1) * 8,
                               pol_last);
                compute2(rA);
                // load even step j+2 while computing odd step j+1
                if (j + 2 < NSTEP)
                    rA = ld_cache4(ct + ((j + 2) >> 1) * 512, pol_last);
                compute2(rB);
            }
        }

        part4[w][lane] = make_float4(ax, ay, az, aw);
        __syncthreads();

        // Reduce the 32 warp-partials: 128 threads, one per (o,p)
        if (tid < NO * NP) {
            const float* pf = (const float*)part4;
            float s = 0.f;
#pragma unroll
            for (int ww = 0; ww < NWARPS; ++ww)
                s += pf[ww * (NO * NP) + tid];
            s_sh[tid] = s;
        }
        __syncthreads();

        // Squash per output capsule (32 threads)
        if (tid < NO) {
            float sx = s_sh[tid * 4 + 0];
            float sy = s_sh[tid * 4 + 1];
            float sz = s_sh[tid * 4 + 2];
            float sw = s_sh[tid * 4 + 3];
            float n2 = sx * sx + sy * sy + sz * sz + sw * sw + EPSF;
            // v = (n2/(1+n2)) * s/sqrt(n2)  ==  s * sqrt(n2)/(1+n2)
            float f  = sqrtf(n2) / (1.0f + n2);
            float vx = sx * f, vy = sy * f, vz = sz * f, vw = sw * f;
            if (it < 2) {
                vsh4[tid] = make_float4(vx, vy, vz, vw);
            } else {
                float* po = out + ((size_t)b * NO + tid) * NP;
                po[0] = vx; po[1] = vy; po[2] = vz; po[3] = vw;
                float a2 = vx * vx + vy * vy + vz * vz + vw * vw + EPSF;
                out[(size_t)NB * NO * NP + (size_t)b * NO + tid] = sqrtf(a2);
            }
        }
        __syncthreads();

        if (it < 2) {
            float4 vnew = vsh4[lane];
            wvs.x = fmaf(vnew.x, l2e, wvs.x);
            wvs.y = fmaf(vnew.y, l2e, wvs.y);
            wvs.z = fmaf(vnew.z, l2e, wvs.z);
            wvs.w = fmaf(vnew.w, l2e, wvs.w);
        }
    }
}

extern "C" void kernel_launch(void* const* d_in, const int* in_sizes, int n_in,
                              void* d_out, int out_size) {
    const float4* votes = (const float4*)d_in[0];   // [B, I, O, P] fp32, 16B-aligned
    // d_in[1] = activations_in — unused by the reference computation
    float* out = (float*)d_out;
    routing_kernel<<<NB, NTHREADS>>>(votes, out);
}

// round 14
// speedup vs baseline: 2.6444x; 2.6444x over previous
#include <cuda_runtime.h>
#include <cuda_fp16.h>

// DynamicRouting: B=128, IN=2048, OUT=32, POSE=4, 3 routing iterations.
// poses_out [B,32,4] followed by activations_out [B,32] in d_out.
//
// R9 skeleton (proven): pass 0 reads fp32 votes (streaming, evict_first),
// writes an fp16 copy into a 64 MB __device__ scratch (evict_last ->
// L2-resident); hot passes 1-2 read one LDG.256 per 4 votes, consumed
// in-body (NO explicit prefetch pipelining - that demotes to local memory
// and triples DRAM traffic, see R11-R13).
// New in R14: paired reciprocal (one MUFU.RCP per 2 votes) and a single
// pre-scaled logit vector wvS = (v1[+v2])*log2e per pass with the +10
// fixed-point bias folded into the dot-product init.

#define NB 128
#define NI 2048
#define NO 32
#define NP 4
#define EPSF 1e-7f
#define NWARPS 32
#define NTHREADS (NWARPS * 32)
#define NQUAD 16            // quads per thread: i = w + 32*(4q+h), h=0..3

typedef unsigned long long u64;
typedef unsigned int u32;

// 64 MB fp16 vote cache, 32B-slot layout. Thread-private RAW (each thread
// re-reads exactly the slots it wrote), phases separated by __syncthreads.
__device__ __align__(32) __half vcache[(size_t)NB * NI * NO * NP];

__device__ __forceinline__ u32 h2_to_u32(__half2 h) {
    union { __half2 h; u32 u; } cvt; cvt.h = h; return cvt.u;
}
__device__ __forceinline__ __half2 u32_to_h2(u32 u) {
    union { u32 u; __half2 h; } cvt; cvt.u = u; return cvt.h;
}
__device__ __forceinline__ float ex2_fast(float x) {
    float r;
    asm("ex2.approx.ftz.f32 %0, %1;" : "=f"(r) : "f"(x));
    return r;
}
__device__ __forceinline__ float rcp_fast(float x) {
    float r;
    asm("rcp.approx.ftz.f32 %0, %1;" : "=f"(r) : "f"(x));
    return r;
}

// fp32 vote load: read-only, streaming (evict_first).
__device__ __forceinline__ float4 ldg_stream(const float4* p, u64 pol) {
    float4 v;
    asm("ld.global.nc.L2::cache_hint.v4.f32 {%0,%1,%2,%3}, [%4], %5;"
        : "=f"(v.x), "=f"(v.y), "=f"(v.z), "=f"(v.w)
        : "l"(p), "l"(pol));
    return v;
}
// 16-byte scratch store with evict_last policy.
__device__ __forceinline__ void st_cache4(__half* p, u32 a, u32 b, u32 c, u32 d, u64 pol) {
    asm volatile("st.global.L2::cache_hint.v4.b32 [%0], {%1,%2,%3,%4}, %5;"
                 :: "l"(p), "r"(a), "r"(b), "r"(c), "r"(d), "l"(pol)
                 : "memory");
}
// 32-byte scratch load (LDG.256), evict_last.
__device__ __forceinline__ void ld_cache8(const __half* p, u32* r) {
    asm("ld.global.nc.L2::evict_last.v8.b32 {%0,%1,%2,%3,%4,%5,%6,%7}, [%8];"
        : "=r"(r[0]), "=r"(r[1]), "=r"(r[2]), "=r"(r[3]),
          "=r"(r[4]), "=r"(r[5]), "=r"(r[6]), "=r"(r[7])
        : "l"(p));
}

__global__ __launch_bounds__(NTHREADS, 1)
void routing_kernel(const float4* __restrict__ votes, float* __restrict__ out) {
    const int b    = blockIdx.x;
    const int tid  = threadIdx.x;
    const int w    = tid >> 5;
    const int lane = tid & 31;      // lane == output-capsule index o

    __shared__ float4 part4[NWARPS][NO];   // per-warp partial s: 16 KB
    __shared__ float4 vsh4[2][NO];         // v1, v2
    __shared__ float  s_sh[NO * NP];       // reduced s

    u64 pol_first, pol_last;
    asm("createpolicy.fractional.L2::evict_first.b64 %0, 1.0;" : "=l"(pol_first));
    asm("createpolicy.fractional.L2::evict_last.b64 %0, 1.0;"  : "=l"(pol_last));

    const float4* vb = votes + (size_t)b * (NI * NO);
    // Thread's scratch: slot(q) at ct + q*512 halves.
    __half* ct = vcache + (size_t)b * (NI * NO * NP)
                        + ((size_t)(w * NQUAD) * 32 + lane) * 16;

    float4 v1 = make_float4(0.f, 0.f, 0.f, 0.f);
    float4 v2 = make_float4(0.f, 0.f, 0.f, 0.f);

#pragma unroll
    for (int it = 0; it < 3; ++it) {
        float ax = 0.f, ay = 0.f, az = 0.f, aw = 0.f;

        if (it == 0) {
            // fp32 streaming pass; uniform c = 1/32; write fp16 cache.
#pragma unroll 2
            for (int q = 0; q < NQUAD; ++q) {
                u32 pk[8];
#pragma unroll
                for (int h = 0; h < 4; ++h) {
                    const int i = w + 32 * (4 * q + h);
                    float4 vt = ldg_stream(&vb[i * NO + lane], pol_first);
                    pk[2 * h + 0] = h2_to_u32(__floats2half2_rn(vt.x, vt.y));
                    pk[2 * h + 1] = h2_to_u32(__floats2half2_rn(vt.z, vt.w));
                    ax += vt.x; ay += vt.y; az += vt.z; aw += vt.w;
                }
                __half* sp = ct + (size_t)q * 512;
                st_cache4(sp,     pk[0], pk[1], pk[2], pk[3], pol_last);
                st_cache4(sp + 8, pk[4], pk[5], pk[6], pk[7], pol_last);
            }
            ax *= (1.0f / 32.0f); ay *= (1.0f / 32.0f);
            az *= (1.0f / 32.0f); aw *= (1.0f / 32.0f);
        } else {
            // Pre-scaled logit vector for this pass: wvS = (v1[+v2])*log2e.
            const float l2e = 1.44269504f;
            float4 wvS;
            if (it == 1) {
                wvS = make_float4(v1.x * l2e, v1.y * l2e,
                                  v1.z * l2e, v1.w * l2e);
            } else {
                wvS = make_float4((v1.x + v2.x) * l2e, (v1.y + v2.y) * l2e,
                                  (v1.z + v2.z) * l2e, (v1.w + v2.w) * l2e);
            }
#pragma unroll 2
            for (int q = 0; q < NQUAD; ++q) {
                u32 pk[8];
                ld_cache8(ct + (size_t)q * 512, pk);
                // Process votes in pairs: one RCP serves two softmax denoms.
#pragma unroll
                for (int h = 0; h < 4; h += 2) {
                    float2 a01 = __half22float2(u32_to_h2(pk[2 * h + 0]));
                    float2 a23 = __half22float2(u32_to_h2(pk[2 * h + 1]));
                    float2 b01 = __half22float2(u32_to_h2(pk[2 * h + 2]));
                    float2 b23 = __half22float2(u32_to_h2(pk[2 * h + 3]));
                    float t0 = 10.0f;               // 2^10 bias folded in
                    t0 = fmaf(a01.x, wvS.x, t0);
                    t0 = fmaf(a01.y, wvS.y, t0);
                    t0 = fmaf(a23.x, wvS.z, t0);
                    t0 = fmaf(a23.y, wvS.w, t0);
                    float t1 = 10.0f;
                    t1 = fmaf(b01.x, wvS.x, t1);
                    t1 = fmaf(b01.y, wvS.y, t1);
                    t1 = fmaf(b23.x, wvS.z, t1);
                    t1 = fmaf(b23.y, wvS.w, t1);
                    float ef0 = ex2_fast(t0);       // e^bij * 2^10
                    float ef1 = ex2_fast(t1);
                    u32 s0 = __reduce_add_sync(0xffffffffu, __float2uint_rn(ef0));
                    u32 s1 = __reduce_add_sync(0xffffffffu, __float2uint_rn(ef1));
                    float sf0 = fmaxf(__uint2float_rn(s0), 1.0f);
                    float sf1 = fmaxf(__uint2float_rn(s1), 1.0f);
                    float inv = rcp_fast(sf0 * sf1);
                    float c0  = ef0 * sf1 * inv;    // = ef0/sf0
                    float c1  = ef1 * sf0 * inv;    // = ef1/sf1
                    ax = fmaf(c0, a01.x, ax);
                    ay = fmaf(c0, a01.y, ay);
                    az = fmaf(c0, a23.x, az);
                    aw = fmaf(c0, a23.y, aw);
                    ax = fmaf(c1, b01.x, ax);
                    ay = fmaf(c1, b01.y, ay);
                    az = fmaf(c1, b23.x, az);
                    aw = fmaf(c1, b23.y, aw);
                }
            }
        }

        part4[w][lane] = make_float4(ax, ay, az, aw);
        __syncthreads();

        // Reduce the 32 warp-partials: 128 threads, one per (o,p)
        if (tid < NO * NP) {
            const float* pf = (const float*)part4;
            float s = 0.f;
#pragma unroll
            for (int ww = 0; ww < NWARPS; ++ww)
                s += pf[ww * (NO * NP) + tid];
            s_sh[tid] = s;
        }
        __syncthreads();

        // Squash per output capsule (32 threads)
        if (tid < NO) {
            float sx = s_sh[tid * 4 + 0];
            float sy = s_sh[tid * 4 + 1];
            float sz = s_sh[tid * 4 + 2];
            float sw = s_sh[tid * 4 + 3];
            float n2 = sx * sx + sy * sy + sz * sz + sw * sw + EPSF;
            // v = (n2/(1+n2)) * s/sqrt(n2)  ==  s * sqrt(n2)/(1+n2)
            float f  = sqrtf(n2) / (1.0f + n2);
            float vx = sx * f, vy = sy * f, vz = sz * f, vw = sw * f;
            if (it < 2) {
                vsh4[it][tid] = make_float4(vx, vy, vz, vw);
            } else {
                float* po = out + ((size_t)b * NO + tid) * NP;
                po[0] = vx; po[1] = vy; po[2] = vz; po[3] = vw;
                float a2 = vx * vx + vy * vy + vz * vz + vw * vw + EPSF;
                out[(size_t)NB * NO * NP + (size_t)b * NO + tid] = sqrtf(a2);
            }
        }
        __syncthreads();

        if (it == 0) v1 = vsh4[0][lane];
        else if (it == 1) v2 = vsh4[1][lane];
    }
}

extern "C" void kernel_launch(void* const* d_in, const int* in_sizes, int n_in,
                              void* d_out, int out_size) {
    const float4* votes = (const float4*)d_in[0];   // [B, I, O, P] fp32, 16B-aligned
    // d_in[1] = activations_in — unused by the reference computation
    float* out = (float*)d_out;
    routing_kernel<<<NB, NTHREADS>>>(votes, out);
}

// round 16
// speedup vs baseline: 2.8771x; 1.0880x over previous
#include <cuda_runtime.h>
#include <cuda_fp16.h>

// DynamicRouting: B=128, IN=2048, OUT=32, POSE=4, 3 routing iterations.
// poses_out [B,32,4] followed by activations_out [B,32] in d_out.
//
// Proven R14 skeleton: pass 0 reads fp32 votes (streaming, evict_first),
// writes an fp16 copy into a 64 MB __device__ scratch (evict_last ->
// L2-resident); hot passes 1-2 read one LDG.256 per 4 votes, consumed
// in-body. Paired reciprocal (one MUFU.RCP per 2 votes), integer REDUX.SUM
// on 2^10 fixed-point exp, pre-scaled logit vector wvS = (v1[+v2])*log2e.
//
// R16 change: v1/v2 live ONLY in shared memory (not registers). This frees
// 8 registers in the hot loop (R14 was pinned at the 64-reg cap), giving
// ptxas the slack to software-pipeline the unroll-2 quad bodies itself.
// (All manual prefetch forms - register ping-pong and cp.async - failed:
// spills at the cap / correctness. Compiler-scheduled overlap is the only
// remaining legal path.)

#define NB 128
#define NI 2048
#define NO 32
#define NP 4
#define EPSF 1e-7f
#define NWARPS 32
#define NTHREADS (NWARPS * 32)
#define NQUAD 16            // quads per thread: i = w + 32*(4q+h), h=0..3

typedef unsigned long long u64;
typedef unsigned int u32;

// 64 MB fp16 vote cache, 32B-slot layout. Thread-private RAW (each thread
// re-reads exactly the slots it wrote), phases separated by __syncthreads.
__device__ __align__(32) __half vcache[(size_t)NB * NI * NO * NP];

__device__ __forceinline__ u32 h2_to_u32(__half2 h) {
    union { __half2 h; u32 u; } cvt; cvt.h = h; return cvt.u;
}
__device__ __forceinline__ __half2 u32_to_h2(u32 u) {
    union { u32 u; __half2 h; } cvt; cvt.u = u; return cvt.h;
}
__device__ __forceinline__ float ex2_fast(float x) {
    float r;
    asm("ex2.approx.ftz.f32 %0, %1;" : "=f"(r) : "f"(x));
    return r;
}
__device__ __forceinline__ float rcp_fast(float x) {
    float r;
    asm("rcp.approx.ftz.f32 %0, %1;" : "=f"(r) : "f"(x));
    return r;
}

// fp32 vote load: read-only, streaming (evict_first).
__device__ __forceinline__ float4 ldg_stream(const float4* p, u64 pol) {
    float4 v;
    asm("ld.global.nc.L2::cache_hint.v4.f32 {%0,%1,%2,%3}, [%4], %5;"
        : "=f"(v.x), "=f"(v.y), "=f"(v.z), "=f"(v.w)
        : "l"(p), "l"(pol));
    return v;
}
// 16-byte scratch store with evict_last policy.
__device__ __forceinline__ void st_cache4(__half* p, u32 a, u32 b, u32 c, u32 d, u64 pol) {
    asm volatile("st.global.L2::cache_hint.v4.b32 [%0], {%1,%2,%3,%4}, %5;"
                 :: "l"(p), "r"(a), "r"(b), "r"(c), "r"(d), "l"(pol)
                 : "memory");
}
// 32-byte scratch load (LDG.256), evict_last.
__device__ __forceinline__ void ld_cache8(const __half* p, u32* r) {
    asm("ld.global.nc.L2::evict_last.v8.b32 {%0,%1,%2,%3,%4,%5,%6,%7}, [%8];"
        : "=r"(r[0]), "=r"(r[1]), "=r"(r[2]), "=r"(r[3]),
          "=r"(r[4]), "=r"(r[5]), "=r"(r[6]), "=r"(r[7])
        : "l"(p));
}

__global__ __launch_bounds__(NTHREADS, 1)
void routing_kernel(const float4* __restrict__ votes, float* __restrict__ out) {
    const int b    = blockIdx.x;
    const int tid  = threadIdx.x;
    const int w    = tid >> 5;
    const int lane = tid & 31;      // lane == output-capsule index o

    __shared__ float4 part4[NWARPS][NO];   // per-warp partial s: 16 KB
    __shared__ float4 vsh4[2][NO];         // v1, v2 (smem ONLY - not in regs)
    __shared__ float  s_sh[NO * NP];       // reduced s

    u64 pol_first, pol_last;
    asm("createpolicy.fractional.L2::evict_first.b64 %0, 1.0;" : "=l"(pol_first));
    asm("createpolicy.fractional.L2::evict_last.b64 %0, 1.0;"  : "=l"(pol_last));

    const float4* vb = votes + (size_t)b * (NI * NO);
    // Thread's scratch: slot(q) at ct + q*512 halves.
    __half* ct = vcache + (size_t)b * (NI * NO * NP)
                        + ((size_t)(w * NQUAD) * 32 + lane) * 16;

#pragma unroll
    for (int it = 0; it < 3; ++it) {
        float ax = 0.f, ay = 0.f, az = 0.f, aw = 0.f;

        if (it == 0) {
            // fp32 streaming pass; uniform c = 1/32; write fp16 cache.
#pragma unroll 2
            for (int q = 0; q < NQUAD; ++q) {
                u32 pk[8];
#pragma unroll
                for (int h = 0; h < 4; ++h) {
                    const int i = w + 32 * (4 * q + h);
                    float4 vt = ldg_stream(&vb[i * NO + lane], pol_first);
                    pk[2 * h + 0] = h2_to_u32(__floats2half2_rn(vt.x, vt.y));
                    pk[2 * h + 1] = h2_to_u32(__floats2half2_rn(vt.z, vt.w));
                    ax += vt.x; ay += vt.y; az += vt.z; aw += vt.w;
                }
                __half* sp = ct + (size_t)q * 512;
                st_cache4(sp,     pk[0], pk[1], pk[2], pk[3], pol_last);
                st_cache4(sp + 8, pk[4], pk[5], pk[6], pk[7], pol_last);
            }
            ax *= (1.0f / 32.0f); ay *= (1.0f / 32.0f);
            az *= (1.0f / 32.0f); aw *= (1.0f / 32.0f);
        } else {
            // Build pre-scaled logit vector from SMEM (v1/v2 never held in
            // registers across the hot loop): wvS = (v1[+v2])*log2e.
            const float l2e = 1.44269504f;
            float4 wvS;
            {
                float4 a = vsh4[0][lane];
                if (it == 2) {
                    float4 c = vsh4[1][lane];
                    a.x += c.x; a.y += c.y; a.z += c.z; a.w += c.w;
                }
                wvS = make_float4(a.x * l2e, a.y * l2e, a.z * l2e, a.w * l2e);
            }
#pragma unroll 2
            for (int q = 0; q < NQUAD; ++q) {
                u32 pk[8];
                ld_cache8(ct + (size_t)q * 512, pk);
                // Process votes in pairs: one RCP serves two softmax denoms.
#pragma unroll
                for (int h = 0; h < 4; h += 2) {
                    float2 a01 = __half22float2(u32_to_h2(pk[2 * h + 0]));
                    float2 a23 = __half22float2(u32_to_h2(pk[2 * h + 1]));
                    float2 b01 = __half22float2(u32_to_h2(pk[2 * h + 2]));
                    float2 b23 = __half22float2(u32_to_h2(pk[2 * h + 3]));
                    float t0 = 10.0f;               // 2^10 bias folded in
                    t0 = fmaf(a01.x, wvS.x, t0);
                    t0 = fmaf(a01.y, wvS.y, t0);
                    t0 = fmaf(a23.x, wvS.z, t0);
                    t0 = fmaf(a23.y, wvS.w, t0);
                    float t1 = 10.0f;
                    t1 = fmaf(b01.x, wvS.x, t1);
                    t1 = fmaf(b01.y, wvS.y, t1);
                    t1 = fmaf(b23.x, wvS.z, t1);
                    t1 = fmaf(b23.y, wvS.w, t1);
                    float ef0 = ex2_fast(t0);       // e^bij * 2^10
                    float ef1 = ex2_fast(t1);
                    u32 s0 = __reduce_add_sync(0xffffffffu, __float2uint_rn(ef0));
                    u32 s1 = __reduce_add_sync(0xffffffffu, __float2uint_rn(ef1));
                    float sf0 = fmaxf(__uint2float_rn(s0), 1.0f);
                    float sf1 = fmaxf(__uint2float_rn(s1), 1.0f);
                    float inv = rcp_fast(sf0 * sf1);
                    float c0  = ef0 * sf1 * inv;    // = ef0/sf0
                    float c1  = ef1 * sf0 * inv;    // = ef1/sf1
                    ax = fmaf(c0, a01.x, ax);
                    ay = fmaf(c0, a01.y, ay);
                    az = fmaf(c0, a23.x, az);
                    aw = fmaf(c0, a23.y, aw);
                    ax = fmaf(c1, b01.x, ax);
                    ay = fmaf(c1, b01.y, ay);
                    az = fmaf(c1, b23.x, az);
                    aw = fmaf(c1, b23.y, aw);
                }
            }
        }

        part4[w][lane] = make_float4(ax, ay, az, aw);
        __syncthreads();

        // Reduce the 32 warp-partials: 128 threads, one per (o,p)
        if (tid < NO * NP) {
            const float* pf = (const float*)part4;
            float s = 0.f;
#pragma unroll
            for (int ww = 0; ww < NWARPS; ++ww)
                s += pf[ww * (NO * NP) + tid];
            s_sh[tid] = s;
        }
        __syncthreads();

        // Squash per output capsule (32 threads)
        if (tid < NO) {
            float sx = s_sh[tid * 4 + 0];
            float sy = s_sh[tid * 4 + 1];
            float sz = s_sh[tid * 4 + 2];
            float sw = s_sh[tid * 4 + 3];
            float n2 = sx * sx + sy * sy + sz * sz + sw * sw + EPSF;
            // v = (n2/(1+n2)) * s/sqrt(n2)  ==  s * sqrt(n2)/(1+n2)
            float f  = sqrtf(n2) / (1.0f + n2);
            float vx = sx * f, vy = sy * f, vz = sz * f, vw = sw * f;
            if (it < 2) {
                vsh4[it][tid] = make_float4(vx, vy, vz, vw);
            } else {
                float* po = out + ((size_t)b * NO + tid) * NP;
                po[0] = vx; po[1] = vy; po[2] = vz; po[3] = vw;
                float a2 = vx * vx + vy * vy + vz * vz + vw * vw + EPSF;
                out[(size_t)NB * NO * NP + (size_t)b * NO + tid] = sqrtf(a2);
            }
        }
        __syncthreads();
    }
}

extern "C" void kernel_launch(void* const* d_in, const int* in_sizes, int n_in,
                              void* d_out, int out_size) {
    const float4* votes = (const float4*)d_in[0];   // [B, I, O, P] fp32, 16B-aligned
    // d_in[1] = activations_in — unused by the reference computation
    float* out = (float*)d_out;
    routing_kernel<<<NB, NTHREADS>>>(votes, out);
}